// round 5
// baseline (speedup 1.0000x reference)
#include <cuda_runtime.h>

#define NN 100000
#define EE 3200000
#define D 128
#define ALPHA 0.2f
#define LN_EPS 1e-5f

// ---- scratch (static device arrays; no allocation allowed) ----
__device__ float g_h[(size_t)NN * D];     // 51.2 MB  (x @ W^T + b)
__device__ float g_s1[NN];
__device__ float g_s2[NN];
__device__ float g_Wt[D * D];             // W transposed: Wt[k][c] = W[c][k]
__device__ int   g_deg[NN];
__device__ int   g_beg[NN];               // region start per src node
__device__ int   g_cur[NN];
__device__ int   g_csr_dst[EE];           // 12.8 MB
__device__ int   g_counter;

// ---------------------------------------------------------------
// 1. prep: transpose W + zero degree histogram + reset counter
// ---------------------------------------------------------------
__global__ void prep_kernel(const float* __restrict__ W, int n) {
    int i = blockIdx.x * blockDim.x + threadIdx.x;
    if (i < D * D) {
        int k = i / D, c = i % D;
        g_Wt[k * D + c] = W[c * D + k];
    }
    if (i < n) g_deg[i] = 0;
    if (i == 0) g_counter = 0;
}

// ---------------------------------------------------------------
// 2. histogram of src degrees  (edge is int32)
// ---------------------------------------------------------------
__global__ void hist_kernel(const int* __restrict__ edge, int E) {
    int e = blockIdx.x * blockDim.x + threadIdx.x;
    if (e < E) {
        int src = edge[e];
        atomicAdd(&g_deg[src], 1);
    }
}

// ---------------------------------------------------------------
// 3. region assignment: block scan of degrees + one global atomic
//    per block. Regions contiguous per node; inter-node order
//    arbitrary (segment_sum is order-insensitive).
// ---------------------------------------------------------------
__global__ __launch_bounds__(256) void offsets_kernel(int n) {
    __shared__ int warp_sums[8];
    __shared__ int sh_base;
    const int tid = threadIdx.x;
    const int i = blockIdx.x * 256 + tid;
    const int lane = tid & 31, wid = tid >> 5;

    int v = (i < n) ? g_deg[i] : 0;
    int incl = v;
    #pragma unroll
    for (int o = 1; o < 32; o <<= 1) {
        int t = __shfl_up_sync(0xffffffffu, incl, o);
        if (lane >= o) incl += t;
    }
    if (lane == 31) warp_sums[wid] = incl;
    __syncthreads();
    if (wid == 0) {
        int ws = (lane < 8) ? warp_sums[lane] : 0;
        int wincl = ws;
        #pragma unroll
        for (int o = 1; o < 8; o <<= 1) {
            int t = __shfl_up_sync(0xffffffffu, wincl, o);
            if (lane >= o) wincl += t;
        }
        if (lane < 8) warp_sums[lane] = wincl - ws;   // exclusive prefix
        if (lane == 7) sh_base = atomicAdd(&g_counter, wincl);
    }
    __syncthreads();
    if (i < n) {
        int beg = sh_base + warp_sums[wid] + (incl - v);
        g_beg[i] = beg;
        g_cur[i] = beg;
    }
}

// ---------------------------------------------------------------
// 4. scatter edges into grouped-by-src order; store dst
// ---------------------------------------------------------------
__global__ void scatter_kernel(const int* __restrict__ edge, int E) {
    int e = blockIdx.x * blockDim.x + threadIdx.x;
    if (e < E) {
        int src = edge[e];
        int dst = edge[E + e];
        int pos = atomicAdd(&g_cur[src], 1);
        g_csr_dst[pos] = dst;
    }
}

// ---------------------------------------------------------------
// 5. GEMM: h = x @ W^T + b, plus s1 = h@a1, s2 = h@a2 in epilogue
//    128 rows x 128 cols per block, 256 threads, thread tile 8x8
// ---------------------------------------------------------------
#define BM 128
#define BK 32
__global__ __launch_bounds__(256) void gemm_kernel(
    const float* __restrict__ x, const float* __restrict__ b,
    const float* __restrict__ a, int nrows)
{
    __shared__ float xs[BK][132];     // [kk][row], stride 132 floats (16B-aligned rows)
    __shared__ float ws[BK][D];       // [kk][col]
    __shared__ float red1[BM];
    __shared__ float red2[BM];
    const int tid = threadIdx.x;
    const int tx = tid & 15, ty = tid >> 4;
    const int r0 = ty * 8, c0 = tx * 8;
    const int row0 = blockIdx.x * BM;

    float acc[8][8];
    #pragma unroll
    for (int r = 0; r < 8; r++)
        #pragma unroll
        for (int j = 0; j < 8; j++) acc[r][j] = 0.f;

    for (int k0 = 0; k0 < D; k0 += BK) {
        // x tile: 128 rows x 32 k, transposed into xs[kk][row]
        #pragma unroll
        for (int i = 0; i < 16; i++) {
            int lin = tid + i * 256;          // 0..4095
            int r = lin >> 5, kk = lin & 31;
            int row = row0 + r;
            xs[kk][r] = (row < nrows) ? x[(size_t)row * D + k0 + kk] : 0.f;
        }
        // W tile: 32 k x 128 c, coalesced from transposed Wt
        #pragma unroll
        for (int i = 0; i < 16; i++) {
            int lin = tid + i * 256;          // 0..4095
            int kk = lin >> 7, c = lin & 127;
            ws[kk][c] = g_Wt[(k0 + kk) * D + c];
        }
        __syncthreads();
        #pragma unroll
        for (int kk = 0; kk < BK; kk++) {
            float4 x0 = *(const float4*)&xs[kk][r0];
            float4 x1 = *(const float4*)&xs[kk][r0 + 4];
            float4 w0 = *(const float4*)&ws[kk][c0];
            float4 w1 = *(const float4*)&ws[kk][c0 + 4];
            float xr[8] = {x0.x, x0.y, x0.z, x0.w, x1.x, x1.y, x1.z, x1.w};
            float wr[8] = {w0.x, w0.y, w0.z, w0.w, w1.x, w1.y, w1.z, w1.w};
            #pragma unroll
            for (int r = 0; r < 8; r++)
                #pragma unroll
                for (int j = 0; j < 8; j++)
                    acc[r][j] += xr[r] * wr[j];
        }
        __syncthreads();
    }

    float bv[8], a1v[8], a2v[8];
    #pragma unroll
    for (int j = 0; j < 8; j++) {
        bv[j]  = b[c0 + j];
        a1v[j] = a[c0 + j];
        a2v[j] = a[D + c0 + j];
    }

    #pragma unroll
    for (int r = 0; r < 8; r++) {
        int row = row0 + r0 + r;
        float v[8];
        float p1 = 0.f, p2 = 0.f;
        #pragma unroll
        for (int j = 0; j < 8; j++) {
            v[j] = acc[r][j] + bv[j];
            p1 += v[j] * a1v[j];
            p2 += v[j] * a2v[j];
        }
        if (row < nrows) {
            float* hp = &g_h[(size_t)row * D + c0];
            *(float4*)(hp)     = make_float4(v[0], v[1], v[2], v[3]);
            *(float4*)(hp + 4) = make_float4(v[4], v[5], v[6], v[7]);
        }
        // reduce p1,p2 across the 16 tx lanes (xor offsets stay in-half)
        #pragma unroll
        for (int o = 8; o > 0; o >>= 1) {
            p1 += __shfl_xor_sync(0xffffffffu, p1, o);
            p2 += __shfl_xor_sync(0xffffffffu, p2, o);
        }
        if (tx == 0) { red1[r0 + r] = p1; red2[r0 + r] = p2; }
    }
    __syncthreads();
    if (tid < BM) {
        int row = row0 + tid;
        if (row < nrows) { g_s1[row] = red1[tid]; g_s2[row] = red2[tid]; }
    }
}

// ---------------------------------------------------------------
// 6. aggregate (warp per node, register accumulator, no atomics)
//    x2 unrolled gather for MLP; fused LayerNorm + ELU
// ---------------------------------------------------------------
__global__ __launch_bounds__(256) void aggregate_ln_kernel(
    const float* __restrict__ ln_w, const float* __restrict__ ln_b,
    float* __restrict__ out, int nrows)
{
    int g = blockIdx.x * blockDim.x + threadIdx.x;
    int n = g >> 5, lane = g & 31;
    if (n >= nrows) return;

    int beg = g_beg[n];
    int end = beg + g_deg[n];
    float s1n = g_s1[n];

    float ax = 0.f, ay = 0.f, az = 0.f, aw = 0.f;
    int p = beg;
    for (; p + 2 <= end; p += 2) {
        int d0 = g_csr_dst[p];
        int d1 = g_csr_dst[p + 1];
        float z0 = s1n + g_s2[d0];
        float z1 = s1n + g_s2[d1];
        float4 hv0 = *(const float4*)&g_h[(size_t)d0 * D + lane * 4];
        float4 hv1 = *(const float4*)&g_h[(size_t)d1 * D + lane * 4];
        float w0 = __expf(-fmaxf(z0, ALPHA * z0));   // exp(-leaky_relu(z))
        float w1 = __expf(-fmaxf(z1, ALPHA * z1));
        ax += w0 * hv0.x + w1 * hv1.x;
        ay += w0 * hv0.y + w1 * hv1.y;
        az += w0 * hv0.z + w1 * hv1.z;
        aw += w0 * hv0.w + w1 * hv1.w;
    }
    if (p < end) {
        int d0 = g_csr_dst[p];
        float z0 = s1n + g_s2[d0];
        float w0 = __expf(-fmaxf(z0, ALPHA * z0));
        float4 hv0 = *(const float4*)&g_h[(size_t)d0 * D + lane * 4];
        ax += w0 * hv0.x;
        ay += w0 * hv0.y;
        az += w0 * hv0.z;
        aw += w0 * hv0.w;
    }

    // LayerNorm (register two-pass) + ELU
    float s = ax + ay + az + aw;
    #pragma unroll
    for (int o = 16; o > 0; o >>= 1) s += __shfl_xor_sync(0xffffffffu, s, o);
    float mu = s * (1.0f / 128.0f);
    float dx = ax - mu, dy = ay - mu, dz = az - mu, dw = aw - mu;
    float ss = dx * dx + dy * dy + dz * dz + dw * dw;
    #pragma unroll
    for (int o = 16; o > 0; o >>= 1) ss += __shfl_xor_sync(0xffffffffu, ss, o);
    float rstd = rsqrtf(ss * (1.0f / 128.0f) + LN_EPS);

    int c = lane * 4;
    float4 lw = *(const float4*)&ln_w[c];
    float4 lb = *(const float4*)&ln_b[c];
    float o0 = dx * rstd * lw.x + lb.x;
    float o1 = dy * rstd * lw.y + lb.y;
    float o2 = dz * rstd * lw.z + lb.z;
    float o3 = dw * rstd * lw.w + lb.w;
    o0 = (o0 > 0.f) ? o0 : expm1f(o0);
    o1 = (o1 > 0.f) ? o1 : expm1f(o1);
    o2 = (o2 > 0.f) ? o2 : expm1f(o2);
    o3 = (o3 > 0.f) ? o3 : expm1f(o3);
    *(float4*)&out[(size_t)n * D + c] = make_float4(o0, o1, o2, o3);
}

// ---------------------------------------------------------------
extern "C" void kernel_launch(void* const* d_in, const int* in_sizes, int n_in,
                              void* d_out, int out_size) {
    const float* x    = (const float*)d_in[0];
    const float* W    = (const float*)d_in[1];
    const float* b    = (const float*)d_in[2];
    const float* a    = (const float*)d_in[3];
    const float* ln_w = (const float*)d_in[4];
    const float* ln_b = (const float*)d_in[5];
    const int*   edge = (const int*)d_in[6];     // int32 (JAX x64 disabled)

    int nrows = in_sizes[0] / D;
    int E     = in_sizes[6] / 2;
    float* out = (float*)d_out;

    prep_kernel<<<(nrows + 255) / 256, 256>>>(W, nrows);
    hist_kernel<<<(E + 255) / 256, 256>>>(edge, E);
    offsets_kernel<<<(nrows + 255) / 256, 256>>>(nrows);
    scatter_kernel<<<(E + 255) / 256, 256>>>(edge, E);
    gemm_kernel<<<(nrows + BM - 1) / BM, 256>>>(x, b, a, nrows);
    aggregate_ln_kernel<<<(nrows * 32 + 255) / 256, 256>>>(ln_w, ln_b, out, nrows);
}

// round 6
// speedup vs baseline: 1.4256x; 1.4256x over previous
#include <cuda_runtime.h>

#define NN 100000
#define EE 3200000
#define D 128
#define ALPHA 0.2f
#define LN_EPS 1e-5f

// ---- scratch (static device arrays; no allocation allowed) ----
__device__ float g_h[(size_t)NN * D];     // 51.2 MB  (x @ W^T + b)
__device__ float g_s1[NN];
__device__ float g_s2[NN];
__device__ float g_Wt[D * D];             // W transposed: Wt[k][c] = W[c][k]
__device__ int   g_deg[NN];
__device__ int   g_beg[NN];               // region start per src node
__device__ int   g_cur[NN];
__device__ int   g_csr_dst[EE];           // 12.8 MB
__device__ int   g_counter;

// ---------------------------------------------------------------
// 1. prep: transpose W + zero degree histogram + reset counter
// ---------------------------------------------------------------
__global__ void prep_kernel(const float* __restrict__ W, int n) {
    int i = blockIdx.x * blockDim.x + threadIdx.x;
    if (i < D * D) {
        int k = i / D, c = i % D;
        g_Wt[k * D + c] = W[c * D + k];
    }
    if (i < n) g_deg[i] = 0;
    if (i == 0) g_counter = 0;
}

// ---------------------------------------------------------------
// 2. histogram of src degrees (4 edges/thread, int4 loads)
// ---------------------------------------------------------------
__global__ void hist_kernel(const int* __restrict__ edge, int E) {
    int e = (blockIdx.x * blockDim.x + threadIdx.x) * 4;
    if (e + 4 <= E) {
        int4 s = *(const int4*)&edge[e];
        atomicAdd(&g_deg[s.x], 1);
        atomicAdd(&g_deg[s.y], 1);
        atomicAdd(&g_deg[s.z], 1);
        atomicAdd(&g_deg[s.w], 1);
    } else {
        for (; e < E; e++) atomicAdd(&g_deg[edge[e]], 1);
    }
}

// ---------------------------------------------------------------
// 3. region assignment: block scan of degrees + one global atomic
//    per block. Regions contiguous per node; inter-node order
//    arbitrary (segment_sum is order-insensitive).
// ---------------------------------------------------------------
__global__ __launch_bounds__(256) void offsets_kernel(int n) {
    __shared__ int warp_sums[8];
    __shared__ int sh_base;
    const int tid = threadIdx.x;
    const int i = blockIdx.x * 256 + tid;
    const int lane = tid & 31, wid = tid >> 5;

    int v = (i < n) ? g_deg[i] : 0;
    int incl = v;
    #pragma unroll
    for (int o = 1; o < 32; o <<= 1) {
        int t = __shfl_up_sync(0xffffffffu, incl, o);
        if (lane >= o) incl += t;
    }
    if (lane == 31) warp_sums[wid] = incl;
    __syncthreads();
    if (wid == 0) {
        int ws = (lane < 8) ? warp_sums[lane] : 0;
        int wincl = ws;
        #pragma unroll
        for (int o = 1; o < 8; o <<= 1) {
            int t = __shfl_up_sync(0xffffffffu, wincl, o);
            if (lane >= o) wincl += t;
        }
        if (lane < 8) warp_sums[lane] = wincl - ws;   // exclusive prefix
        if (lane == 7) sh_base = atomicAdd(&g_counter, wincl);
    }
    __syncthreads();
    if (i < n) {
        int beg = sh_base + warp_sums[wid] + (incl - v);
        g_beg[i] = beg;
        g_cur[i] = beg;
    }
}

// ---------------------------------------------------------------
// 4. scatter edges into grouped-by-src order (4 edges/thread)
// ---------------------------------------------------------------
__global__ void scatter_kernel(const int* __restrict__ edge, int E) {
    int e = (blockIdx.x * blockDim.x + threadIdx.x) * 4;
    if (e + 4 <= E) {
        int4 s = *(const int4*)&edge[e];
        int4 d = *(const int4*)&edge[E + e];
        g_csr_dst[atomicAdd(&g_cur[s.x], 1)] = d.x;
        g_csr_dst[atomicAdd(&g_cur[s.y], 1)] = d.y;
        g_csr_dst[atomicAdd(&g_cur[s.z], 1)] = d.z;
        g_csr_dst[atomicAdd(&g_cur[s.w], 1)] = d.w;
    } else {
        for (; e < E; e++) {
            int src = edge[e];
            int dst = edge[E + e];
            g_csr_dst[atomicAdd(&g_cur[src], 1)] = dst;
        }
    }
}

// ---------------------------------------------------------------
// 5. GEMM: h = x @ W^T + b, plus s1 = h@a1, s2 = h@a2 in epilogue
//    64 rows x 128 cols per block, 256 threads, thread tile 4x8
//    (R4 proven config; shfl-xor epilogue reduction)
// ---------------------------------------------------------------
__global__ __launch_bounds__(256) void gemm_kernel(
    const float* __restrict__ x, const float* __restrict__ b,
    const float* __restrict__ a, int nrows)
{
    __shared__ float xs[32][68];      // [kk][row], padded (272B rows, 16B-aligned)
    __shared__ float ws[32][128];     // [kk][col]
    __shared__ float red1[64];
    __shared__ float red2[64];
    const int tid = threadIdx.x;
    const int row0 = blockIdx.x * 64;
    const int tx = tid & 15, ty = tid >> 4;
    const int r0 = ty * 4, c0 = tx * 8;

    float acc[4][8];
    #pragma unroll
    for (int r = 0; r < 4; r++)
        #pragma unroll
        for (int j = 0; j < 8; j++) acc[r][j] = 0.f;

    for (int k0 = 0; k0 < D; k0 += 32) {
        #pragma unroll
        for (int i = 0; i < 8; i++) {
            int lin = tid + i * 256;          // 0..2047
            int r = lin >> 5, kk = lin & 31;
            int row = row0 + r;
            xs[kk][r] = (row < nrows) ? x[(size_t)row * D + k0 + kk] : 0.f;
        }
        #pragma unroll
        for (int i = 0; i < 16; i++) {
            int lin = tid + i * 256;          // 0..4095
            int kk = lin >> 7, c = lin & 127;
            ws[kk][c] = g_Wt[(k0 + kk) * D + c];
        }
        __syncthreads();
        #pragma unroll
        for (int kk = 0; kk < 32; kk++) {
            float4 xv = *(const float4*)&xs[kk][r0];
            float4 w0 = *(const float4*)&ws[kk][c0];
            float4 w1 = *(const float4*)&ws[kk][c0 + 4];
            float xr[4] = {xv.x, xv.y, xv.z, xv.w};
            float wr[8] = {w0.x, w0.y, w0.z, w0.w, w1.x, w1.y, w1.z, w1.w};
            #pragma unroll
            for (int r = 0; r < 4; r++)
                #pragma unroll
                for (int j = 0; j < 8; j++)
                    acc[r][j] += xr[r] * wr[j];
        }
        __syncthreads();
    }

    float bv[8], a1v[8], a2v[8];
    #pragma unroll
    for (int j = 0; j < 8; j++) {
        bv[j]  = b[c0 + j];
        a1v[j] = a[c0 + j];
        a2v[j] = a[D + c0 + j];
    }

    #pragma unroll
    for (int r = 0; r < 4; r++) {
        int row = row0 + r0 + r;
        float v[8];
        float p1 = 0.f, p2 = 0.f;
        #pragma unroll
        for (int j = 0; j < 8; j++) {
            v[j] = acc[r][j] + bv[j];
            p1 += v[j] * a1v[j];
            p2 += v[j] * a2v[j];
        }
        if (row < nrows) {
            float* hp = &g_h[(size_t)row * D + c0];
            *(float4*)(hp)     = make_float4(v[0], v[1], v[2], v[3]);
            *(float4*)(hp + 4) = make_float4(v[4], v[5], v[6], v[7]);
        }
        // reduce across the 16 tx lanes (xor 8..1 stays within tx group)
        #pragma unroll
        for (int o = 8; o > 0; o >>= 1) {
            p1 += __shfl_xor_sync(0xffffffffu, p1, o);
            p2 += __shfl_xor_sync(0xffffffffu, p2, o);
        }
        if (tx == 0) { red1[r0 + r] = p1; red2[r0 + r] = p2; }
    }
    __syncthreads();
    if (tid < 64) {
        int row = row0 + tid;
        if (row < nrows) { g_s1[row] = red1[tid]; g_s2[row] = red2[tid]; }
    }
}

// ---------------------------------------------------------------
// 6. aggregate (warp per node, register accumulator, no atomics)
//    x2 unrolled gather for MLP; fused LayerNorm + ELU
// ---------------------------------------------------------------
__global__ __launch_bounds__(256) void aggregate_ln_kernel(
    const float* __restrict__ ln_w, const float* __restrict__ ln_b,
    float* __restrict__ out, int nrows)
{
    int g = blockIdx.x * blockDim.x + threadIdx.x;
    int n = g >> 5, lane = g & 31;
    if (n >= nrows) return;

    int beg = g_beg[n];
    int end = beg + g_deg[n];
    float s1n = g_s1[n];

    float ax = 0.f, ay = 0.f, az = 0.f, aw = 0.f;
    int p = beg;
    for (; p + 2 <= end; p += 2) {
        int d0 = g_csr_dst[p];
        int d1 = g_csr_dst[p + 1];
        float z0 = s1n + g_s2[d0];
        float z1 = s1n + g_s2[d1];
        float4 hv0 = *(const float4*)&g_h[(size_t)d0 * D + lane * 4];
        float4 hv1 = *(const float4*)&g_h[(size_t)d1 * D + lane * 4];
        float w0 = __expf(-fmaxf(z0, ALPHA * z0));   // exp(-leaky_relu(z))
        float w1 = __expf(-fmaxf(z1, ALPHA * z1));
        ax += w0 * hv0.x + w1 * hv1.x;
        ay += w0 * hv0.y + w1 * hv1.y;
        az += w0 * hv0.z + w1 * hv1.z;
        aw += w0 * hv0.w + w1 * hv1.w;
    }
    if (p < end) {
        int d0 = g_csr_dst[p];
        float z0 = s1n + g_s2[d0];
        float w0 = __expf(-fmaxf(z0, ALPHA * z0));
        float4 hv0 = *(const float4*)&g_h[(size_t)d0 * D + lane * 4];
        ax += w0 * hv0.x;
        ay += w0 * hv0.y;
        az += w0 * hv0.z;
        aw += w0 * hv0.w;
    }

    // LayerNorm (register two-pass) + ELU
    float s = ax + ay + az + aw;
    #pragma unroll
    for (int o = 16; o > 0; o >>= 1) s += __shfl_xor_sync(0xffffffffu, s, o);
    float mu = s * (1.0f / 128.0f);
    float dx = ax - mu, dy = ay - mu, dz = az - mu, dw = aw - mu;
    float ss = dx * dx + dy * dy + dz * dz + dw * dw;
    #pragma unroll
    for (int o = 16; o > 0; o >>= 1) ss += __shfl_xor_sync(0xffffffffu, ss, o);
    float rstd = rsqrtf(ss * (1.0f / 128.0f) + LN_EPS);

    int c = lane * 4;
    float4 lw = *(const float4*)&ln_w[c];
    float4 lb = *(const float4*)&ln_b[c];
    float o0 = dx * rstd * lw.x + lb.x;
    float o1 = dy * rstd * lw.y + lb.y;
    float o2 = dz * rstd * lw.z + lb.z;
    float o3 = dw * rstd * lw.w + lb.w;
    o0 = (o0 > 0.f) ? o0 : expm1f(o0);
    o1 = (o1 > 0.f) ? o1 : expm1f(o1);
    o2 = (o2 > 0.f) ? o2 : expm1f(o2);
    o3 = (o3 > 0.f) ? o3 : expm1f(o3);
    *(float4*)&out[(size_t)n * D + c] = make_float4(o0, o1, o2, o3);
}

// ---------------------------------------------------------------
extern "C" void kernel_launch(void* const* d_in, const int* in_sizes, int n_in,
                              void* d_out, int out_size) {
    const float* x    = (const float*)d_in[0];
    const float* W    = (const float*)d_in[1];
    const float* b    = (const float*)d_in[2];
    const float* a    = (const float*)d_in[3];
    const float* ln_w = (const float*)d_in[4];
    const float* ln_b = (const float*)d_in[5];
    const int*   edge = (const int*)d_in[6];     // int32 (JAX x64 disabled)

    int nrows = in_sizes[0] / D;
    int E     = in_sizes[6] / 2;
    float* out = (float*)d_out;

    prep_kernel<<<(nrows + 255) / 256, 256>>>(W, nrows);
    hist_kernel<<<(E / 4 + 255) / 256, 256>>>(edge, E);
    offsets_kernel<<<(nrows + 255) / 256, 256>>>(nrows);
    scatter_kernel<<<(E / 4 + 255) / 256, 256>>>(edge, E);
    gemm_kernel<<<(nrows + 63) / 64, 256>>>(x, b, a, nrows);
    aggregate_ln_kernel<<<(nrows * 32 + 255) / 256, 256>>>(ln_w, ln_b, out, nrows);
}